// round 10
// baseline (speedup 1.0000x reference)
#include <cuda_runtime.h>
#include <cuda_bf16.h>
#include <cstdint>

typedef unsigned char uchar;
typedef unsigned short ushort;
typedef __nv_bfloat16 bf16;

#define NB 8

// ---------------- device scratch ----------------
__device__ __align__(16) bf16 g_wk1[1024 * 1536];
__device__ __align__(16) bf16 g_wq1[160 * 240];
__device__ __align__(16) bf16 g_wk2[80 * 1024];
__device__ __align__(16) bf16 g_wq2[80 * 160];
__device__ __align__(16) bf16 g_wq3[80 * 80];
__device__ __align__(16) bf16 g_phon [NB * 512 * 272];     // halo-padded, XS=272
__device__ __align__(16) bf16 g_audio[NB * 80 * 1040];     // halo-padded, XS=1040
__device__ __align__(16) bf16 g_H1b[NB * 1024 * 256];
__device__ __align__(16) bf16 g_H2b[NB * 160 * 1000 + 64];
__device__ __align__(16) bf16 g_H3b[NB * 80 * 1000 + 64];
__device__ __align__(16) float g_keysP[8 * NB * 80 * 256]; // split-K partials (x8)
__device__ __align__(16) bf16  g_keysBf[NB * 80 * 256];
__device__ __align__(16) float g_Q[NB * 80 * 1000];
__device__ int g_maskmode;                                 // 0=u8, 1=i32, 2=f32

union U8 { uint4 v; ushort u[8]; };

// ---------------- fused prep (4 elems/thread): convert + pad + mask detect --
__global__ void prep_kernel(
    const float* __restrict__ kw1, const float* __restrict__ qw1,
    const float* __restrict__ kw2, const float* __restrict__ qw2,
    const float* __restrict__ qw3, const float* __restrict__ phon,
    const float* __restrict__ aud, const uchar* __restrict__ mask)
{
    if (blockIdx.x == 0 && threadIdx.x == 0) {
        const unsigned* d = (const unsigned*)mask;
        bool i32 = true, f32 = true;
        for (int i = 0; i < 256; i++) {
            unsigned v = d[i];
            if (v != 0u && v != 1u) i32 = false;
            if (v != 0u && v != 0x3F800000u) f32 = false;
        }
        g_maskmode = i32 ? 1 : (f32 ? 2 : 0);
    }
    long i = ((long)blockIdx.x * 256 + threadIdx.x) * 4;
    const long N1 = 1024L * 1536, N2 = 160 * 240, N3 = 80 * 1024,
               N4 = 80 * 160, N5 = 80 * 80;
    const long NP = 8L * 512 * 272, NA = 8L * 80 * 1040;

    // weight regions: 4-aligned chunks never cross region boundaries
    const float* src = nullptr; bf16* dst = nullptr;
    if (i < N1) { src = kw1; dst = g_wk1; }
    else if ((i -= N1) < N2) { src = qw1; dst = g_wq1; }
    else if ((i -= N2) < N3) { src = kw2; dst = g_wk2; }
    else if ((i -= N3) < N4) { src = qw2; dst = g_wq2; }
    else if ((i -= N4) < N5) { src = qw3; dst = g_wq3; }
    if (src) {
        float4 v = *(const float4*)(src + i);
        *(__nv_bfloat162*)(dst + i)     = __floats2bfloat162_rn(v.x, v.y);
        *(__nv_bfloat162*)(dst + i + 2) = __floats2bfloat162_rn(v.z, v.w);
        return;
    }
    i -= N5;
    if (i < NP) {   // phonemes: rows of 272, valid x in [1,256]
        long r = i / 272; int x0 = (int)(i - r * 272);
#pragma unroll
        for (int e = 0; e < 4; e++) {
            int x = x0 + e;
            g_phon[i + e] = (x >= 1 && x <= 256)
                ? __float2bfloat16(phon[r * 256 + x - 1]) : __float2bfloat16(0.f);
        }
        return;
    }
    i -= NP;
    if (i < NA) {   // audio: rows of 1040, valid x in [1,1000]
        long r = i / 1040; int x0 = (int)(i - r * 1040);
#pragma unroll
        for (int e = 0; e < 4; e++) {
            int x = x0 + e;
            g_audio[i + e] = (x >= 1 && x <= 1000)
                ? __float2bfloat16(aud[r * 1000 + x - 1]) : __float2bfloat16(0.f);
        }
    }
}

// ---------------- mma helpers ----------------
__device__ __forceinline__ uint32_t smem_u32(const void* p) {
    return (uint32_t)__cvta_generic_to_shared(p);
}
__device__ __forceinline__ void ldsm4(uint32_t& r0, uint32_t& r1,
                                      uint32_t& r2, uint32_t& r3, uint32_t a) {
    asm volatile("ldmatrix.sync.aligned.m8n8.x4.shared.b16 {%0,%1,%2,%3}, [%4];"
                 : "=r"(r0), "=r"(r1), "=r"(r2), "=r"(r3) : "r"(a));
}
__device__ __forceinline__ void ldsm4t(uint32_t& r0, uint32_t& r1,
                                       uint32_t& r2, uint32_t& r3, uint32_t a) {
    asm volatile("ldmatrix.sync.aligned.m8n8.x4.trans.shared.b16 {%0,%1,%2,%3}, [%4];"
                 : "=r"(r0), "=r"(r1), "=r"(r2), "=r"(r3) : "r"(a));
}
__device__ __forceinline__ void mma16816(float c[4], const uint32_t a[4],
                                         uint32_t b0, uint32_t b1) {
    asm volatile(
        "mma.sync.aligned.m16n8k16.row.col.f32.bf16.bf16.f32 "
        "{%0,%1,%2,%3}, {%4,%5,%6,%7}, {%8,%9}, {%0,%1,%2,%3};"
        : "+f"(c[0]), "+f"(c[1]), "+f"(c[2]), "+f"(c[3])
        : "r"(a[0]), "r"(a[1]), "r"(a[2]), "r"(a[3]), "r"(b0), "r"(b1));
}

template <int BSTR, int TN>
__device__ __forceinline__ void storeB3(ushort* Brow, int pbase, uint4 v) {
    U8 u; u.v = v;
#pragma unroll
    for (int kw = 0; kw < 3; kw++)
#pragma unroll
        for (int j = 0; j < 8; j++) {
            int t = pbase + j - kw;
            if (t >= 0 && t < TN) Brow[kw * BSTR + t] = u.u[j];
        }
}

// ---------------- job descriptor (runtime-dispatched conv) -------------------
struct Job {
    const bf16* W; const float* bias; const bf16* X; char* Y;
    int M, T, XS, Ktot, kLen, nbx, nby, flags;  // flags: 1=relu, 2=outBf16, 4=split
};

// ---------------------------------------------------------------------------
// Pipelined bf16 tensor-core conv-as-GEMM body (double-buffered, 1 sync/iter).
// ---------------------------------------------------------------------------
template <int KW, int TKC, int TN, int WMI, int WNJ>
__device__ __forceinline__ void conv_body(const Job j, int bx, int by, int b)
{
    constexpr int TM = 128;
    constexpr int TK = TKC * KW;
    constexpr int KSTEPS = TK / 16;
    constexpr int ASTR = TK + 8;
    constexpr int BSTR = TN + 8;
    constexpr int WARPSN = TN / (16 * WNJ);
    constexpr int ACH = (TM * TK) / 2048;
    constexpr int AKCH = TK / 8;

    extern __shared__ __align__(16) bf16 dsm[];
    bf16* Asm = dsm;
    bf16* Bsm = dsm + 2 * TM * ASTR;

    const bool relu = j.flags & 1, outBf = j.flags & 2, split = j.flags & 4;
    const int tid = threadIdx.x, lane = tid & 31, wid = tid >> 5;
    const int m0 = split ? 0 : by * TM;
    const int kb = split ? by * j.kLen : 0;
    const int kLim = min(kb + j.kLen, j.Ktot);
    const int Cin = j.Ktot / KW;
    const int t0 = bx * TN;
    const int wm = (wid / WARPSN) * (WMI * 16);
    const int wn = (wid % WARPSN) * (WNJ * 16);
    const bf16* Xb = j.X + (long)b * Cin * j.XS;
    const int Ktot = j.Ktot, M = j.M, T = j.T, XS = j.XS;

    const uint32_t AsU = smem_u32(Asm);
    const uint32_t BsU = smem_u32(Bsm);

    float acc[WMI][WNJ * 2][4];
#pragma unroll
    for (int mi = 0; mi < WMI; mi++)
#pragma unroll
        for (int jj = 0; jj < WNJ * 2; jj++)
#pragma unroll
            for (int c = 0; c < 4; c++) acc[mi][jj][c] = 0.f;

    const int iters = (kLim - kb + TK - 1) / TK;

    uint4 aR[ACH];
    uint4 bR0;

    auto loadA = [&](int it) {
#pragma unroll
        for (int r = 0; r < ACH; r++) {
            int cid = tid + 256 * r;
            int row = cid / AKCH;
            int ch  = (cid % AKCH) * 8;
            int gm = m0 + row;
            int gk = kb + it * TK + ch;
            uint4 v = make_uint4(0u, 0u, 0u, 0u);
            if (gm < M && gk < kLim) v = *(const uint4*)(j.W + (long)gm * Ktot + gk);
            aR[r] = v;
        }
    };
    auto storeA = [&](int p) {
#pragma unroll
        for (int r = 0; r < ACH; r++) {
            int cid = tid + 256 * r;
            int row = cid / AKCH;
            int ch  = (cid % AKCH) * 8;
            *(uint4*)(Asm + p * TM * ASTR + row * ASTR + ch) = aR[r];
        }
    };
    auto loadB = [&](int it) {
        if constexpr (KW == 1) {
            int kk = tid >> 3, seg = tid & 7;
            int c = kb + it * TK + kk;
            uint4 v = make_uint4(0u, 0u, 0u, 0u);
            if (c < kLim) v = *(const uint4*)(Xb + (long)c * XS + t0 + seg * 8);
            bR0 = v;
        } else {
            int r = tid >> 4, seg = tid & 15;
            constexpr int CHB = (TN + 16) / 8;
            if (seg < CHB) {
                const bf16* rowp = Xb + (long)(it * TKC + r) * XS + t0;
                bR0 = *(const uint4*)(rowp + seg * 8);
            }
        }
    };
    auto storeB = [&](int p) {
        if constexpr (KW == 1) {
            int kk = tid >> 3, seg = tid & 7;
            *(uint4*)(Bsm + p * TK * BSTR + kk * BSTR + seg * 8) = bR0;
        } else {
            int r = tid >> 4, seg = tid & 15;
            constexpr int CHB = (TN + 16) / 8;
            if (seg < CHB) {
                ushort* Brow = (ushort*)(Bsm + p * TK * BSTR + (r * 3) * BSTR);
                storeB3<BSTR, TN>(Brow, seg * 8, bR0);
            }
        }
    };
    auto compute = [&](int p) {
#pragma unroll
        for (int ks = 0; ks < KSTEPS; ks++) {
            uint32_t a[WMI][4];
#pragma unroll
            for (int mi = 0; mi < WMI; mi++) {
                uint32_t addr = AsU + (uint32_t)(p * TM * ASTR +
                    (wm + mi * 16 + (lane & 15)) * ASTR + ks * 16 + (lane >> 4) * 8) * 2;
                ldsm4(a[mi][0], a[mi][1], a[mi][2], a[mi][3], addr);
            }
            uint32_t bb[WNJ][4];
#pragma unroll
            for (int nj = 0; nj < WNJ; nj++) {
                uint32_t addr = BsU + (uint32_t)(p * TK * BSTR +
                    (ks * 16 + (lane & 15)) * BSTR + wn + nj * 16 + (lane >> 4) * 8) * 2;
                ldsm4t(bb[nj][0], bb[nj][1], bb[nj][2], bb[nj][3], addr);
            }
#pragma unroll
            for (int mi = 0; mi < WMI; mi++)
#pragma unroll
                for (int nj = 0; nj < WNJ; nj++) {
                    mma16816(acc[mi][nj * 2 + 0], a[mi], bb[nj][0], bb[nj][1]);
                    mma16816(acc[mi][nj * 2 + 1], a[mi], bb[nj][2], bb[nj][3]);
                }
        }
    };

    loadA(0); loadB(0);
    storeA(0); storeB(0);
    __syncthreads();
    for (int it = 0; it < iters; it++) {
        int p = it & 1;
        if (it + 1 < iters) { loadA(it + 1); loadB(it + 1); }
        compute(p);
        if (it + 1 < iters) {
            storeA(1 - p); storeB(1 - p);
            __syncthreads();
        }
    }

    // epilogue
    const int g = lane >> 2, tig = lane & 3;
#pragma unroll
    for (int mi = 0; mi < WMI; mi++)
#pragma unroll
        for (int h = 0; h < 2; h++) {
            int gm = m0 + wm + mi * 16 + g + h * 8;
            if (gm >= M) continue;
            float bv = (split && by != 0) ? 0.f : j.bias[gm];
            long rowoff;
            if (split) rowoff = ((long)(by * NB + b) * M + gm) * T;
            else       rowoff = ((long)b * M + gm) * T;
#pragma unroll
            for (int jj = 0; jj < WNJ * 2; jj++) {
                int t = t0 + wn + jj * 8 + tig * 2;
                if (t >= T) continue;
                float v0 = acc[mi][jj][h * 2 + 0] + bv;
                float v1 = acc[mi][jj][h * 2 + 1] + bv;
                if (relu) { v0 = fmaxf(v0, 0.f); v1 = fmaxf(v1, 0.f); }
                if (outBf)
                    *(__nv_bfloat162*)((bf16*)j.Y + rowoff + t) = __floats2bfloat162_rn(v0, v1);
                else
                    *(float2*)((float*)j.Y + rowoff + t) = make_float2(v0, v1);
            }
        }
}

__device__ __forceinline__ void decode(const Job& j, int local, int& bx, int& by, int& bz)
{
    bx = local % j.nbx;
    int rem = local / j.nbx;
    by = rem % j.nby;
    bz = rem / j.nby;
}

// L2: both k=3 convs in one launch
__global__ void __launch_bounds__(256) conv3_dual(Job j0, Job j1, int n0)
{
    int bid = blockIdx.x;
    Job j = (bid < n0) ? j0 : j1;
    int local = (bid < n0) ? bid : bid - n0;
    int bx, by, bz; decode(j, local, bx, by, bz);
    conv_body<3, 16, 64, 2, 2>(j, bx, by, bz);
}

// L3/L4: 1x1 convs (+ optional keys split-K reduce blocks at the tail)
__global__ void __launch_bounds__(256) conv1_multi(Job j0, Job j1, int n0, int ntot, int nParts)
{
    int bid = blockIdx.x;
    if (bid >= ntot) {      // reduce blocks
        int i = ((bid - ntot) * 256 + threadIdx.x) * 4;
        const int N = NB * 80 * 256;
        if (i < N) {
            float4 s = *(const float4*)&g_keysP[i];
            for (int p = 1; p < nParts; p++) {
                float4 t = *(const float4*)&g_keysP[(long)p * N + i];
                s.x += t.x; s.y += t.y; s.z += t.z; s.w += t.w;
            }
            __nv_bfloat162* dst = (__nv_bfloat162*)&g_keysBf[i];
            dst[0] = __floats2bfloat162_rn(s.x, s.y);
            dst[1] = __floats2bfloat162_rn(s.z, s.w);
        }
        return;
    }
    Job j = (bid < n0) ? j0 : j1;
    int local = (bid < n0) ? bid : bid - n0;
    int bx, by, bz; decode(j, local, bx, by, bz);
    conv_body<1, 32, 64, 2, 2>(j, bx, by, bz);
}

// ---------------------------------------------------------------------------
// attention: out = log_softmax(-T*|q-k|^2) + log(prior+1e-8); !mask -> -inf.
// ---------------------------------------------------------------------------
__global__ void __launch_bounds__(256) attn_kernel(
    const float* __restrict__ prior, const void* __restrict__ maskraw,
    float* __restrict__ out)
{
    __shared__ __align__(16) bf16 ks[80 * 256];
    __shared__ float k2s[256];
    __shared__ float qs[8 * 80];

    const int b = blockIdx.y;
    const int tid = threadIdx.x;
    const int mode = g_maskmode;
    const bf16* keysb = g_keysBf + (long)b * 80 * 256;

    for (int i = tid; i < 80 * 256 / 8; i += 256)
        ((uint4*)ks)[i] = ((const uint4*)keysb)[i];
    __syncthreads();
    {
        int t = tid;
        float s = 0.f;
#pragma unroll 8
        for (int c = 0; c < 80; c++) {
            float v = __bfloat162float(ks[c * 256 + t]);
            s += v * v;
        }
        k2s[t] = s;
    }
    __syncthreads();

    const int wid = tid >> 5, lane = tid & 31;
    for (int it = 0; it < 5; it++) {
        int row = blockIdx.x * 40 + it * 8 + wid;
        for (int c = lane; c < 80; c += 32)
            qs[wid * 80 + c] = g_Q[((long)b * 80 + c) * 1000 + row];
        __syncwarp();

        float acc[8];
#pragma unroll
        for (int j = 0; j < 8; j++) acc[j] = 0.f;
#pragma unroll 4
        for (int c = 0; c < 80; c++) {
            float qv = qs[wid * 80 + c];
            uint4 kv = *(const uint4*)&ks[c * 256 + lane * 8];
            float2 f0 = __bfloat1622float2(*(__nv_bfloat162*)&kv.x);
            float2 f1 = __bfloat1622float2(*(__nv_bfloat162*)&kv.y);
            float2 f2 = __bfloat1622float2(*(__nv_bfloat162*)&kv.z);
            float2 f3 = __bfloat1622float2(*(__nv_bfloat162*)&kv.w);
            acc[0] += qv * f0.x; acc[1] += qv * f0.y;
            acc[2] += qv * f1.x; acc[3] += qv * f1.y;
            acc[4] += qv * f2.x; acc[5] += qv * f2.y;
            acc[6] += qv * f3.x; acc[7] += qv * f3.y;
        }

        float s[8];
        float mx = -1e30f;
#pragma unroll
        for (int j = 0; j < 8; j++) {
            s[j] = 0.0005f * (2.f * acc[j] - k2s[lane * 8 + j]);
            mx = fmaxf(mx, s[j]);
        }
#pragma unroll
        for (int o = 16; o > 0; o >>= 1) mx = fmaxf(mx, __shfl_xor_sync(0xffffffffu, mx, o));
        float sum = 0.f;
#pragma unroll
        for (int j = 0; j < 8; j++) sum += __expf(s[j] - mx);
#pragma unroll
        for (int o = 16; o > 0; o >>= 1) sum += __shfl_xor_sync(0xffffffffu, sum, o);
        float lse = mx + __logf(sum);

        long base = ((long)(b * 1000 + row)) * 256 + lane * 8;
        float4 p0 = *(const float4*)(prior + base);
        float4 p1 = *(const float4*)(prior + base + 4);
        const float NEG = __int_as_float(0xff800000);
        float o8[8];
        o8[0] = s[0] - lse + __logf(p0.x + 1e-8f);
        o8[1] = s[1] - lse + __logf(p0.y + 1e-8f);
        o8[2] = s[2] - lse + __logf(p0.z + 1e-8f);
        o8[3] = s[3] - lse + __logf(p0.w + 1e-8f);
        o8[4] = s[4] - lse + __logf(p1.x + 1e-8f);
        o8[5] = s[5] - lse + __logf(p1.y + 1e-8f);
        o8[6] = s[6] - lse + __logf(p1.z + 1e-8f);
        o8[7] = s[7] - lse + __logf(p1.w + 1e-8f);

        if (mode == 1) {
            const int* mp = (const int*)maskraw;
#pragma unroll
            for (int j = 0; j < 8; j++) if (mp[base + j] == 0) o8[j] = NEG;
        } else if (mode == 2) {
            const float* mp = (const float*)maskraw;
#pragma unroll
            for (int j = 0; j < 8; j++) if (mp[base + j] == 0.f) o8[j] = NEG;
        } else {
            const uchar* mp = (const uchar*)maskraw;
            uchar4 m0 = *(const uchar4*)(mp + base);
            uchar4 m1 = *(const uchar4*)(mp + base + 4);
            if (!m0.x) o8[0] = NEG; if (!m0.y) o8[1] = NEG;
            if (!m0.z) o8[2] = NEG; if (!m0.w) o8[3] = NEG;
            if (!m1.x) o8[4] = NEG; if (!m1.y) o8[5] = NEG;
            if (!m1.z) o8[6] = NEG; if (!m1.w) o8[7] = NEG;
        }

        *(float4*)(out + base)     = make_float4(o8[0], o8[1], o8[2], o8[3]);
        *(float4*)(out + base + 4) = make_float4(o8[4], o8[5], o8[6], o8[7]);
        __syncwarp();
    }
}

// ---------------------------------------------------------------------------
extern "C" void kernel_launch(void* const* d_in, const int* in_sizes, int n_in,
                              void* d_out, int out_size)
{
    const float* phonemes = (const float*)d_in[0];
    const float* audio    = (const float*)d_in[1];
    const uchar* mask     = (const uchar*)d_in[2];
    const float* prior    = (const float*)d_in[3];
    const float* kw1 = (const float*)d_in[4];
    const float* kb1 = (const float*)d_in[5];
    const float* kw2 = (const float*)d_in[6];
    const float* kb2 = (const float*)d_in[7];
    const float* qw1 = (const float*)d_in[8];
    const float* qb1 = (const float*)d_in[9];
    const float* qw2 = (const float*)d_in[10];
    const float* qb2 = (const float*)d_in[11];
    const float* qw3 = (const float*)d_in[12];
    const float* qb3 = (const float*)d_in[13];
    float* out = (float*)d_out;

    void* p;
    cudaGetSymbolAddress(&p, g_wk1);    bf16* wk1 = (bf16*)p;
    cudaGetSymbolAddress(&p, g_wq1);    bf16* wq1 = (bf16*)p;
    cudaGetSymbolAddress(&p, g_wk2);    bf16* wk2 = (bf16*)p;
    cudaGetSymbolAddress(&p, g_wq2);    bf16* wq2 = (bf16*)p;
    cudaGetSymbolAddress(&p, g_wq3);    bf16* wq3 = (bf16*)p;
    cudaGetSymbolAddress(&p, g_phon);   bf16* phon = (bf16*)p;
    cudaGetSymbolAddress(&p, g_audio);  bf16* aud  = (bf16*)p;
    cudaGetSymbolAddress(&p, g_H1b);    bf16* H1 = (bf16*)p;
    cudaGetSymbolAddress(&p, g_H2b);    bf16* H2 = (bf16*)p;
    cudaGetSymbolAddress(&p, g_H3b);    bf16* H3 = (bf16*)p;
    cudaGetSymbolAddress(&p, g_keysP);  float* keysP = (float*)p;
    cudaGetSymbolAddress(&p, g_Q);      float* Q = (float*)p;

    const int SMEM_K3 = (2 * 128 * 56 + 2 * 48 * 72) * 2;   // 42496
    const int SMEM_K1 = (2 * 128 * 40 + 2 * 32 * 72) * 2;   // 29696

    // L1: prep (4 elems/thread)
    {
        long total = 1024L * 1536 + 160 * 240 + 80 * 1024 + 80 * 160 + 80 * 80
                   + 8L * 512 * 272 + 8L * 80 * 1040;
        prep_kernel<<<(int)((total / 4 + 255) / 256), 256>>>(
            kw1, qw1, kw2, qw2, qw3, phonemes, audio, mask);
    }

    // L2: kconv1 + qconv1 (merged)
    {
        Job jk1 = { wk1, kb1, phon, (char*)H1, 1024, 256, 272, 1536, 1536, 4, 8, 1 | 2 };
        Job jq1 = { wq1, qb1, aud,  (char*)H2, 160, 1000, 1040, 240, 240, 16, 2, 1 | 2 };
        conv3_dual<<<256 + 256, 256, SMEM_K3>>>(jk1, jq1, 256);
    }

    // L3: kconv2 split-K x8 + qconv2 (merged)
    {
        Job jk2 = { wk2, kb2, H1, (char*)keysP, 80, 256, 256, 1024, 128, 4, 8, 4 };
        Job jq2 = { wq2, qb2, H2, (char*)H3, 80, 1000, 1000, 160, 160, 16, 1, 1 | 2 };
        conv1_multi<<<256 + 128, 256, SMEM_K1>>>(jk2, jq2, 256, 384, 0);
    }

    // L4: qconv3 + keys reduce (merged)
    {
        Job jq3 = { wq3, qb3, H3, (char*)Q, 80, 1000, 1000, 80, 80, 16, 1, 0 };
        conv1_multi<<<128 + 160, 256, SMEM_K1>>>(jq3, jq3, 128, 128, 8);
    }

    // L5: attention + log_softmax + prior + mask
    attn_kernel<<<dim3(25, 8), 256>>>(prior, mask, out);
}

// round 12
// speedup vs baseline: 1.2172x; 1.2172x over previous
#include <cuda_runtime.h>
#include <cuda_bf16.h>
#include <cstdint>

typedef unsigned char uchar;
typedef unsigned short ushort;
typedef __nv_bfloat16 bf16;

#define NB 8

// ---------------- device scratch ----------------
__device__ __align__(16) bf16 g_wk1[1024 * 1536];
__device__ __align__(16) bf16 g_wq1[160 * 240];
__device__ __align__(16) bf16 g_wk2[80 * 1024];
__device__ __align__(16) bf16 g_wq2[80 * 160];
__device__ __align__(16) bf16 g_wq3[80 * 80];
__device__ __align__(16) bf16 g_phon [NB * 512 * 272];     // halo-padded, XS=272
__device__ __align__(16) bf16 g_audio[NB * 80 * 1040];     // halo-padded, XS=1040
__device__ __align__(16) bf16 g_H1b[NB * 1024 * 256];
__device__ __align__(16) bf16 g_H2b[NB * 160 * 1000 + 64];
__device__ __align__(16) bf16 g_H3b[NB * 80 * 1000 + 64];
__device__ __align__(16) float g_keysP[4 * NB * 80 * 256]; // split-K partials (x4)
__device__ __align__(16) bf16  g_keysBf[NB * 80 * 256];
__device__ __align__(16) float g_Q[NB * 80 * 1000];
__device__ int g_maskmode;                                 // 0=u8, 1=i32, 2=f32

union U8 { uint4 v; ushort u[8]; };

// ---------------- fused prep (4 elems/thread): convert + pad + mask detect --
__global__ void prep_kernel(
    const float* __restrict__ kw1, const float* __restrict__ qw1,
    const float* __restrict__ kw2, const float* __restrict__ qw2,
    const float* __restrict__ qw3, const float* __restrict__ phon,
    const float* __restrict__ aud, const uchar* __restrict__ mask)
{
    if (blockIdx.x == 0 && threadIdx.x == 0) {
        const unsigned* d = (const unsigned*)mask;
        bool i32 = true, f32 = true;
        for (int i = 0; i < 256; i++) {
            unsigned v = d[i];
            if (v != 0u && v != 1u) i32 = false;
            if (v != 0u && v != 0x3F800000u) f32 = false;
        }
        g_maskmode = i32 ? 1 : (f32 ? 2 : 0);
    }
    long i = ((long)blockIdx.x * 256 + threadIdx.x) * 4;
    const long N1 = 1024L * 1536, N2 = 160 * 240, N3 = 80 * 1024,
               N4 = 80 * 160, N5 = 80 * 80;
    const long NP = 8L * 512 * 272, NA = 8L * 80 * 1040;

    const float* src = nullptr; bf16* dst = nullptr;
    if (i < N1) { src = kw1; dst = g_wk1; }
    else if ((i -= N1) < N2) { src = qw1; dst = g_wq1; }
    else if ((i -= N2) < N3) { src = kw2; dst = g_wk2; }
    else if ((i -= N3) < N4) { src = qw2; dst = g_wq2; }
    else if ((i -= N4) < N5) { src = qw3; dst = g_wq3; }
    if (src) {
        float4 v = *(const float4*)(src + i);
        *(__nv_bfloat162*)(dst + i)     = __floats2bfloat162_rn(v.x, v.y);
        *(__nv_bfloat162*)(dst + i + 2) = __floats2bfloat162_rn(v.z, v.w);
        return;
    }
    i -= N5;
    if (i < NP) {   // phonemes: rows of 272, valid x in [1,256]
        long r = i / 272; int x0 = (int)(i - r * 272);
#pragma unroll
        for (int e = 0; e < 4; e++) {
            int x = x0 + e;
            g_phon[i + e] = (x >= 1 && x <= 256)
                ? __float2bfloat16(phon[r * 256 + x - 1]) : __float2bfloat16(0.f);
        }
        return;
    }
    i -= NP;
    if (i < NA) {   // audio: rows of 1040, valid x in [1,1000]
        long r = i / 1040; int x0 = (int)(i - r * 1040);
#pragma unroll
        for (int e = 0; e < 4; e++) {
            int x = x0 + e;
            g_audio[i + e] = (x >= 1 && x <= 1000)
                ? __float2bfloat16(aud[r * 1000 + x - 1]) : __float2bfloat16(0.f);
        }
    }
}

// ---------------- mma helpers ----------------
__device__ __forceinline__ uint32_t smem_u32(const void* p) {
    return (uint32_t)__cvta_generic_to_shared(p);
}
__device__ __forceinline__ void ldsm4(uint32_t& r0, uint32_t& r1,
                                      uint32_t& r2, uint32_t& r3, uint32_t a) {
    asm volatile("ldmatrix.sync.aligned.m8n8.x4.shared.b16 {%0,%1,%2,%3}, [%4];"
                 : "=r"(r0), "=r"(r1), "=r"(r2), "=r"(r3) : "r"(a));
}
__device__ __forceinline__ void ldsm4t(uint32_t& r0, uint32_t& r1,
                                       uint32_t& r2, uint32_t& r3, uint32_t a) {
    asm volatile("ldmatrix.sync.aligned.m8n8.x4.trans.shared.b16 {%0,%1,%2,%3}, [%4];"
                 : "=r"(r0), "=r"(r1), "=r"(r2), "=r"(r3) : "r"(a));
}
__device__ __forceinline__ void mma16816(float c[4], const uint32_t a[4],
                                         uint32_t b0, uint32_t b1) {
    asm volatile(
        "mma.sync.aligned.m16n8k16.row.col.f32.bf16.bf16.f32 "
        "{%0,%1,%2,%3}, {%4,%5,%6,%7}, {%8,%9}, {%0,%1,%2,%3};"
        : "+f"(c[0]), "+f"(c[1]), "+f"(c[2]), "+f"(c[3])
        : "r"(a[0]), "r"(a[1]), "r"(a[2]), "r"(a[3]), "r"(b0), "r"(b1));
}

template <int BSTR, int TN>
__device__ __forceinline__ void storeB3(ushort* Brow, int pbase, uint4 v) {
    U8 u; u.v = v;
#pragma unroll
    for (int kw = 0; kw < 3; kw++)
#pragma unroll
        for (int j = 0; j < 8; j++) {
            int t = pbase + j - kw;
            if (t >= 0 && t < TN) Brow[kw * BSTR + t] = u.u[j];
        }
}

// ---------------- job descriptor (runtime-dispatched conv) -------------------
struct Job {
    const bf16* W; const float* bias; const bf16* X; char* Y;
    int M, T, XS, Ktot, kLen, nbx, nby, flags;  // flags: 1=relu, 2=outBf16, 4=split
};

// ---------------------------------------------------------------------------
// Pipelined bf16 tensor-core conv-as-GEMM body (double-buffered, 1 sync/iter).
// ---------------------------------------------------------------------------
template <int KW, int TKC, int TN, int WMI, int WNJ>
__device__ __forceinline__ void conv_body(const Job j, int bx, int by, int b)
{
    constexpr int TM = 128;
    constexpr int TK = TKC * KW;
    constexpr int KSTEPS = TK / 16;
    constexpr int ASTR = TK + 8;
    constexpr int BSTR = TN + 8;
    constexpr int WARPSN = TN / (16 * WNJ);
    constexpr int ACH = (TM * TK) / 2048;
    constexpr int AKCH = TK / 8;

    extern __shared__ __align__(16) bf16 dsm[];
    bf16* Asm = dsm;
    bf16* Bsm = dsm + 2 * TM * ASTR;

    const bool relu = j.flags & 1, outBf = j.flags & 2, split = j.flags & 4;
    const int tid = threadIdx.x, lane = tid & 31, wid = tid >> 5;
    const int m0 = split ? 0 : by * TM;
    const int kb = split ? by * j.kLen : 0;
    const int kLim = min(kb + j.kLen, j.Ktot);
    const int Cin = j.Ktot / KW;
    const int t0 = bx * TN;
    const int wm = (wid / WARPSN) * (WMI * 16);
    const int wn = (wid % WARPSN) * (WNJ * 16);
    const bf16* Xb = j.X + (long)b * Cin * j.XS;
    const int Ktot = j.Ktot, M = j.M, T = j.T, XS = j.XS;

    const uint32_t AsU = smem_u32(Asm);
    const uint32_t BsU = smem_u32(Bsm);

    float acc[WMI][WNJ * 2][4];
#pragma unroll
    for (int mi = 0; mi < WMI; mi++)
#pragma unroll
        for (int jj = 0; jj < WNJ * 2; jj++)
#pragma unroll
            for (int c = 0; c < 4; c++) acc[mi][jj][c] = 0.f;

    const int iters = (kLim - kb + TK - 1) / TK;

    uint4 aR[ACH];
    uint4 bR0, bR1;
    constexpr int CHB = (TN + 16) / 8;

    auto loadA = [&](int it) {
#pragma unroll
        for (int r = 0; r < ACH; r++) {
            int cid = tid + 256 * r;
            int row = cid / AKCH;
            int ch  = (cid % AKCH) * 8;
            int gm = m0 + row;
            int gk = kb + it * TK + ch;
            uint4 v = make_uint4(0u, 0u, 0u, 0u);
            if (gm < M && gk < kLim) v = *(const uint4*)(j.W + (long)gm * Ktot + gk);
            aR[r] = v;
        }
    };
    auto storeA = [&](int p) {
#pragma unroll
        for (int r = 0; r < ACH; r++) {
            int cid = tid + 256 * r;
            int row = cid / AKCH;
            int ch  = (cid % AKCH) * 8;
            *(uint4*)(Asm + p * TM * ASTR + row * ASTR + ch) = aR[r];
        }
    };
    auto loadB = [&](int it) {
        if constexpr (KW == 1) {
            int kk = tid >> 3, seg = tid & 7;
            int c = kb + it * TK + kk;
            uint4 v = make_uint4(0u, 0u, 0u, 0u);
            if (c < kLim) v = *(const uint4*)(Xb + (long)c * XS + t0 + seg * 8);
            bR0 = v;
        } else {
            int r = tid >> 4, seg = tid & 15;
            const bf16* rowp = Xb + (long)(it * TKC + r) * XS + t0;
            if (seg < CHB) bR0 = *(const uint4*)(rowp + seg * 8);
            if constexpr (CHB > 16) {
                if (seg + 16 < CHB) bR1 = *(const uint4*)(rowp + (seg + 16) * 8);
            }
        }
    };
    auto storeB = [&](int p) {
        if constexpr (KW == 1) {
            int kk = tid >> 3, seg = tid & 7;
            *(uint4*)(Bsm + p * TK * BSTR + kk * BSTR + seg * 8) = bR0;
        } else {
            int r = tid >> 4, seg = tid & 15;
            ushort* Brow = (ushort*)(Bsm + p * TK * BSTR + (r * 3) * BSTR);
            if (seg < CHB) storeB3<BSTR, TN>(Brow, seg * 8, bR0);
            if constexpr (CHB > 16) {
                if (seg + 16 < CHB) storeB3<BSTR, TN>(Brow, (seg + 16) * 8, bR1);
            }
        }
    };
    auto compute = [&](int p) {
#pragma unroll
        for (int ks = 0; ks < KSTEPS; ks++) {
            uint32_t a[WMI][4];
#pragma unroll
            for (int mi = 0; mi < WMI; mi++) {
                uint32_t addr = AsU + (uint32_t)(p * TM * ASTR +
                    (wm + mi * 16 + (lane & 15)) * ASTR + ks * 16 + (lane >> 4) * 8) * 2;
                ldsm4(a[mi][0], a[mi][1], a[mi][2], a[mi][3], addr);
            }
            uint32_t bb[WNJ][4];
#pragma unroll
            for (int nj = 0; nj < WNJ; nj++) {
                uint32_t addr = BsU + (uint32_t)(p * TK * BSTR +
                    (ks * 16 + (lane & 15)) * BSTR + wn + nj * 16 + (lane >> 4) * 8) * 2;
                ldsm4t(bb[nj][0], bb[nj][1], bb[nj][2], bb[nj][3], addr);
            }
#pragma unroll
            for (int mi = 0; mi < WMI; mi++)
#pragma unroll
                for (int nj = 0; nj < WNJ; nj++) {
                    mma16816(acc[mi][nj * 2 + 0], a[mi], bb[nj][0], bb[nj][1]);
                    mma16816(acc[mi][nj * 2 + 1], a[mi], bb[nj][2], bb[nj][3]);
                }
        }
    };

    loadA(0); loadB(0);
    storeA(0); storeB(0);
    __syncthreads();
    for (int it = 0; it < iters; it++) {
        int p = it & 1;
        if (it + 1 < iters) { loadA(it + 1); loadB(it + 1); }
        compute(p);
        if (it + 1 < iters) {
            storeA(1 - p); storeB(1 - p);
            __syncthreads();
        }
    }

    // epilogue
    const int g = lane >> 2, tig = lane & 3;
#pragma unroll
    for (int mi = 0; mi < WMI; mi++)
#pragma unroll
        for (int h = 0; h < 2; h++) {
            int gm = m0 + wm + mi * 16 + g + h * 8;
            if (gm >= M) continue;
            float bv = (split && by != 0) ? 0.f : j.bias[gm];
            long rowoff;
            if (split) rowoff = ((long)(by * NB + b) * M + gm) * T;
            else       rowoff = ((long)b * M + gm) * T;
#pragma unroll
            for (int jj = 0; jj < WNJ * 2; jj++) {
                int t = t0 + wn + jj * 8 + tig * 2;
                if (t >= T) continue;
                float v0 = acc[mi][jj][h * 2 + 0] + bv;
                float v1 = acc[mi][jj][h * 2 + 1] + bv;
                if (relu) { v0 = fmaxf(v0, 0.f); v1 = fmaxf(v1, 0.f); }
                if (outBf)
                    *(__nv_bfloat162*)((bf16*)j.Y + rowoff + t) = __floats2bfloat162_rn(v0, v1);
                else
                    *(float2*)((float*)j.Y + rowoff + t) = make_float2(v0, v1);
            }
        }
}

__device__ __forceinline__ void decode(const Job& j, int local, int& bx, int& by, int& bz)
{
    bx = local % j.nbx;
    int rem = local / j.nbx;
    by = rem % j.nby;
    bz = rem / j.nby;
}

// L2: both k=3 convs in one launch, R9-proven config (TN=128, warp tile 64x32)
__global__ void __launch_bounds__(256) conv3_dual(Job j0, Job j1, int n0)
{
    int bid = blockIdx.x;
    Job j = (bid < n0) ? j0 : j1;
    int local = (bid < n0) ? bid : bid - n0;
    int bx, by, bz; decode(j, local, bx, by, bz);
    conv_body<3, 16, 128, 4, 2>(j, bx, by, bz);
}

// L3/L4: 1x1 convs (+ optional keys split-K reduce blocks at the tail)
__global__ void __launch_bounds__(256) conv1_multi(Job j0, Job j1, int n0, int ntot, int nParts)
{
    int bid = blockIdx.x;
    if (bid >= ntot) {      // reduce blocks
        int i = ((bid - ntot) * 256 + threadIdx.x) * 4;
        const int N = NB * 80 * 256;
        if (i < N) {
            float4 s = *(const float4*)&g_keysP[i];
            for (int p = 1; p < nParts; p++) {
                float4 t = *(const float4*)&g_keysP[(long)p * N + i];
                s.x += t.x; s.y += t.y; s.z += t.z; s.w += t.w;
            }
            __nv_bfloat162* dst = (__nv_bfloat162*)&g_keysBf[i];
            dst[0] = __floats2bfloat162_rn(s.x, s.y);
            dst[1] = __floats2bfloat162_rn(s.z, s.w);
        }
        return;
    }
    Job j = (bid < n0) ? j0 : j1;
    int local = (bid < n0) ? bid : bid - n0;
    int bx, by, bz; decode(j, local, bx, by, bz);
    conv_body<1, 32, 64, 2, 2>(j, bx, by, bz);
}

// ---------------------------------------------------------------------------
// attention: out = log_softmax(-T*|q-k|^2) + log(prior+1e-8); !mask -> -inf.
// ---------------------------------------------------------------------------
__global__ void __launch_bounds__(256) attn_kernel(
    const float* __restrict__ prior, const void* __restrict__ maskraw,
    float* __restrict__ out)
{
    __shared__ __align__(16) bf16 ks[80 * 256];
    __shared__ float k2s[256];
    __shared__ float qs[8 * 80];

    const int b = blockIdx.y;
    const int tid = threadIdx.x;
    const int mode = g_maskmode;
    const bf16* keysb = g_keysBf + (long)b * 80 * 256;

    for (int i = tid; i < 80 * 256 / 8; i += 256)
        ((uint4*)ks)[i] = ((const uint4*)keysb)[i];
    __syncthreads();
    {
        int t = tid;
        float s = 0.f;
#pragma unroll 8
        for (int c = 0; c < 80; c++) {
            float v = __bfloat162float(ks[c * 256 + t]);
            s += v * v;
        }
        k2s[t] = s;
    }
    __syncthreads();

    const int wid = tid >> 5, lane = tid & 31;
    for (int it = 0; it < 5; it++) {
        int row = blockIdx.x * 40 + it * 8 + wid;
        for (int c = lane; c < 80; c += 32)
            qs[wid * 80 + c] = g_Q[((long)b * 80 + c) * 1000 + row];
        __syncwarp();

        float acc[8];
#pragma unroll
        for (int j = 0; j < 8; j++) acc[j] = 0.f;
#pragma unroll 4
        for (int c = 0; c < 80; c++) {
            float qv = qs[wid * 80 + c];
            uint4 kv = *(const uint4*)&ks[c * 256 + lane * 8];
            float2 f0 = __bfloat1622float2(*(__nv_bfloat162*)&kv.x);
            float2 f1 = __bfloat1622float2(*(__nv_bfloat162*)&kv.y);
            float2 f2 = __bfloat1622float2(*(__nv_bfloat162*)&kv.z);
            float2 f3 = __bfloat1622float2(*(__nv_bfloat162*)&kv.w);
            acc[0] += qv * f0.x; acc[1] += qv * f0.y;
            acc[2] += qv * f1.x; acc[3] += qv * f1.y;
            acc[4] += qv * f2.x; acc[5] += qv * f2.y;
            acc[6] += qv * f3.x; acc[7] += qv * f3.y;
        }

        float s[8];
        float mx = -1e30f;
#pragma unroll
        for (int j = 0; j < 8; j++) {
            s[j] = 0.0005f * (2.f * acc[j] - k2s[lane * 8 + j]);
            mx = fmaxf(mx, s[j]);
        }
#pragma unroll
        for (int o = 16; o > 0; o >>= 1) mx = fmaxf(mx, __shfl_xor_sync(0xffffffffu, mx, o));
        float sum = 0.f;
#pragma unroll
        for (int j = 0; j < 8; j++) sum += __expf(s[j] - mx);
#pragma unroll
        for (int o = 16; o > 0; o >>= 1) sum += __shfl_xor_sync(0xffffffffu, sum, o);
        float lse = mx + __logf(sum);

        long base = ((long)(b * 1000 + row)) * 256 + lane * 8;
        float4 p0 = *(const float4*)(prior + base);
        float4 p1 = *(const float4*)(prior + base + 4);
        const float NEG = __int_as_float(0xff800000);
        float o8[8];
        o8[0] = s[0] - lse + __logf(p0.x + 1e-8f);
        o8[1] = s[1] - lse + __logf(p0.y + 1e-8f);
        o8[2] = s[2] - lse + __logf(p0.z + 1e-8f);
        o8[3] = s[3] - lse + __logf(p0.w + 1e-8f);
        o8[4] = s[4] - lse + __logf(p1.x + 1e-8f);
        o8[5] = s[5] - lse + __logf(p1.y + 1e-8f);
        o8[6] = s[6] - lse + __logf(p1.z + 1e-8f);
        o8[7] = s[7] - lse + __logf(p1.w + 1e-8f);

        if (mode == 1) {
            const int* mp = (const int*)maskraw;
#pragma unroll
            for (int j = 0; j < 8; j++) if (mp[base + j] == 0) o8[j] = NEG;
        } else if (mode == 2) {
            const float* mp = (const float*)maskraw;
#pragma unroll
            for (int j = 0; j < 8; j++) if (mp[base + j] == 0.f) o8[j] = NEG;
        } else {
            const uchar* mp = (const uchar*)maskraw;
            uchar4 m0 = *(const uchar4*)(mp + base);
            uchar4 m1 = *(const uchar4*)(mp + base + 4);
            if (!m0.x) o8[0] = NEG; if (!m0.y) o8[1] = NEG;
            if (!m0.z) o8[2] = NEG; if (!m0.w) o8[3] = NEG;
            if (!m1.x) o8[4] = NEG; if (!m1.y) o8[5] = NEG;
            if (!m1.z) o8[6] = NEG; if (!m1.w) o8[7] = NEG;
        }

        *(float4*)(out + base)     = make_float4(o8[0], o8[1], o8[2], o8[3]);
        *(float4*)(out + base + 4) = make_float4(o8[4], o8[5], o8[6], o8[7]);
        __syncwarp();
    }
}

// ---------------------------------------------------------------------------
extern "C" void kernel_launch(void* const* d_in, const int* in_sizes, int n_in,
                              void* d_out, int out_size)
{
    const float* phonemes = (const float*)d_in[0];
    const float* audio    = (const float*)d_in[1];
    const uchar* mask     = (const uchar*)d_in[2];
    const float* prior    = (const float*)d_in[3];
    const float* kw1 = (const float*)d_in[4];
    const float* kb1 = (const float*)d_in[5];
    const float* kw2 = (const float*)d_in[6];
    const float* kb2 = (const float*)d_in[7];
    const float* qw1 = (const float*)d_in[8];
    const float* qb1 = (const float*)d_in[9];
    const float* qw2 = (const float*)d_in[10];
    const float* qb2 = (const float*)d_in[11];
    const float* qw3 = (const float*)d_in[12];
    const float* qb3 = (const float*)d_in[13];
    float* out = (float*)d_out;

    void* p;
    cudaGetSymbolAddress(&p, g_wk1);    bf16* wk1 = (bf16*)p;
    cudaGetSymbolAddress(&p, g_wq1);    bf16* wq1 = (bf16*)p;
    cudaGetSymbolAddress(&p, g_wk2);    bf16* wk2 = (bf16*)p;
    cudaGetSymbolAddress(&p, g_wq2);    bf16* wq2 = (bf16*)p;
    cudaGetSymbolAddress(&p, g_wq3);    bf16* wq3 = (bf16*)p;
    cudaGetSymbolAddress(&p, g_phon);   bf16* phon = (bf16*)p;
    cudaGetSymbolAddress(&p, g_audio);  bf16* aud  = (bf16*)p;
    cudaGetSymbolAddress(&p, g_H1b);    bf16* H1 = (bf16*)p;
    cudaGetSymbolAddress(&p, g_H2b);    bf16* H2 = (bf16*)p;
    cudaGetSymbolAddress(&p, g_H3b);    bf16* H3 = (bf16*)p;
    cudaGetSymbolAddress(&p, g_keysP);  float* keysP = (float*)p;
    cudaGetSymbolAddress(&p, g_Q);      float* Q = (float*)p;

    const int SMEM_K3 = (2 * 128 * 56 + 2 * 48 * 136) * 2;  // 54784 (TN=128 config)
    const int SMEM_K1 = (2 * 128 * 40 + 2 * 32 * 72) * 2;   // 29696

    cudaFuncSetAttribute(conv3_dual,
                         cudaFuncAttributeMaxDynamicSharedMemorySize, SMEM_K3);

    // L1: prep (4 elems/thread)
    {
        long total = 1024L * 1536 + 160 * 240 + 80 * 1024 + 80 * 160 + 80 * 80
                   + 8L * 512 * 272 + 8L * 80 * 1040;
        prep_kernel<<<(int)((total / 4 + 255) / 256), 256>>>(
            kw1, qw1, kw2, qw2, qw3, phonemes, audio, mask);
    }

    // L2: kconv1 + qconv1 merged, R9-proven TN=128 config (128 blocks each)
    {
        Job jk1 = { wk1, kb1, phon, (char*)H1, 1024, 256, 272, 1536, 1536, 2, 8, 1 | 2 };
        Job jq1 = { wq1, qb1, aud,  (char*)H2, 160, 1000, 1040, 240, 240, 8, 2, 1 | 2 };
        conv3_dual<<<128 + 128, 256, SMEM_K3>>>(jk1, jq1, 128);
    }

    // L3: kconv2 split-K x4 + qconv2 (merged)
    {
        Job jk2 = { wk2, kb2, H1, (char*)keysP, 80, 256, 256, 1024, 256, 4, 4, 4 };
        Job jq2 = { wq2, qb2, H2, (char*)H3, 80, 1000, 1000, 160, 160, 16, 1, 1 | 2 };
        conv1_multi<<<128 + 128, 256, SMEM_K1>>>(jk2, jq2, 128, 256, 0);
    }

    // L4: qconv3 + keys reduce x4 (merged)
    {
        Job jq3 = { wq3, qb3, H3, (char*)Q, 80, 1000, 1000, 80, 80, 16, 1, 0 };
        conv1_multi<<<128 + 160, 256, SMEM_K1>>>(jq3, jq3, 128, 128, 4);
    }

    // L5: attention + log_softmax + prior + mask
    attn_kernel<<<dim3(25, 8), 256>>>(prior, mask, out);
}